// round 16
// baseline (speedup 1.0000x reference)
#include <cuda_runtime.h>
#include <cuda_bf16.h>
#include <math.h>
#include <stdint.h>

// Bahdanau attention, B=32 S=2048 H=1024.
//   score GEMM v9: mma.sync bf16 3-term split, BK=16, TWO-stage smem
//   double buffer (48KB static exactly), cp.async U staging from pre-split
//   planes (4MB, proven safe), E converted from regs loaded 1 iter ahead.
//   occ 2, ldmatrix, term-major groups. Then softmax + context as before.
// Output: context (32768 f32) then attn (65536 f32).
// Forbidden (container killers / unproven): big __device__ globals (>5MB),
// dynamic smem, cudaFuncSetAttribute, tcgen05.

#define B_  32
#define S_  2048
#define H_  1024
#define M_  (B_ * S_)
#define NOT 8                      // o-tiles of 128
#define NSC 16                     // ctx s-chunks

__device__ float g_wh[B_ * H_];
__device__ float g_spart[NOT * M_];          // 2 MB
__device__ float g_cpart[NSC * B_ * H_];     // 2 MB
__device__ __nv_bfloat16 g_U2hi[H_ * H_];    // 2 MB (proven safe in R13)
__device__ __nv_bfloat16 g_U2lo[H_ * H_];    // 2 MB

// ---------------------------------------------------------------------------
#define MMA16816(d, a, b) \
    asm volatile("mma.sync.aligned.m16n8k16.row.col.f32.bf16.bf16.f32 " \
        "{%0,%1,%2,%3}, {%4,%5,%6,%7}, {%8,%9}, {%0,%1,%2,%3};" \
        : "+f"((d)[0]), "+f"((d)[1]), "+f"((d)[2]), "+f"((d)[3]) \
        : "r"((a)[0]), "r"((a)[1]), "r"((a)[2]), "r"((a)[3]), \
          "r"((b)[0]), "r"((b)[1]))

#define LDSM_X4(r0, r1, r2, r3, addr) \
    asm volatile("ldmatrix.sync.aligned.m8n8.x4.shared.b16 {%0,%1,%2,%3}, [%4];" \
        : "=r"(r0), "=r"(r1), "=r"(r2), "=r"(r3) : "r"(addr))

#define CP_ASYNC16(sa, ga) \
    asm volatile("cp.async.cg.shared.global [%0], [%1], 16;" \
        :: "r"((uint32_t)(sa)), "l"(ga) : "memory")
#define CP_ASYNC_COMMIT() asm volatile("cp.async.commit_group;" ::: "memory")
#define CP_ASYNC_WAIT0()  asm volatile("cp.async.wait_group 0;" ::: "memory")

__device__ __forceinline__ uint32_t smem_u32(const void* p) {
    uint32_t a;
    asm("{ .reg .u64 t; cvta.to.shared.u64 t, %1; cvt.u32.u64 %0, t; }" : "=r"(a) : "l"(p));
    return a;
}

// ---------------------------------------------------------------------------
// FMA-only fast tanh (no MUFU)
// ---------------------------------------------------------------------------
__device__ __forceinline__ float fast_tanh(float x) {
    float xc = fminf(fmaxf(x, -7.90531110763549805f), 7.90531110763549805f);
    float x2 = xc * xc;
    float p = -2.76076847742355e-16f;
    p = fmaf(p, x2, 2.00018790482477e-13f);
    p = fmaf(p, x2, -8.60467152213735e-11f);
    p = fmaf(p, x2, 5.12229709037114e-08f);
    p = fmaf(p, x2, 1.48572235717979e-05f);
    p = fmaf(p, x2, 6.37261928875436e-04f);
    p = fmaf(p, x2, 4.89352455891786e-03f);
    p = p * xc;
    float q = 1.19825839466702e-06f;
    q = fmaf(q, x2, 1.18534705686654e-04f);
    q = fmaf(q, x2, 2.26843463243900e-03f);
    q = fmaf(q, x2, 4.89352518554385e-03f);
    float r = __int_as_float(0x7EF311C3 - __float_as_int(q));
    r = r * fmaf(-q, r, 2.0f);
    r = r * fmaf(-q, r, 2.0f);
    return p * r;
}

// split 8 fp32 -> 16B hi + 16B lo bf16
__device__ __forceinline__ void split_pack8(float4 a, float4 b,
                                            uint4& Hh, uint4& Ll) {
    float f[8] = {a.x, a.y, a.z, a.w, b.x, b.y, b.z, b.w};
    uint32_t h[8], l[8];
#pragma unroll
    for (int i = 0; i < 8; i++) {
        __nv_bfloat16 hb = __float2bfloat16_rn(f[i]);
        __nv_bfloat16 lb = __float2bfloat16_rn(f[i] - __bfloat162float(hb));
        h[i] = (uint32_t)__bfloat16_as_ushort(hb);
        l[i] = (uint32_t)__bfloat16_as_ushort(lb);
    }
    Hh.x = h[0] | (h[1] << 16); Hh.y = h[2] | (h[3] << 16);
    Hh.z = h[4] | (h[5] << 16); Hh.w = h[6] | (h[7] << 16);
    Ll.x = l[0] | (l[1] << 16); Ll.y = l[2] | (l[3] << 16);
    Ll.z = l[4] | (l[5] << 16); Ll.w = l[6] | (l[7] << 16);
}

// ---------------------------------------------------------------------------
__global__ void noop_kernel() {}

__global__ void prep_U_kernel(const float* __restrict__ U) {
    int i = blockIdx.x * 256 + threadIdx.x;
    float4 a = ((const float4*)U)[2 * i];
    float4 b = ((const float4*)U)[2 * i + 1];
    uint4 Hh, Ll;
    split_pack8(a, b, Hh, Ll);
    ((uint4*)g_U2hi)[i] = Hh;
    ((uint4*)g_U2lo)[i] = Ll;
}

__global__ void wh_kernel(const float* __restrict__ hidden,
                          const float* __restrict__ W) {
    int b = blockIdx.x;
    int o = blockIdx.y * 256 + threadIdx.x;
    const float4* h4 = (const float4*)(hidden + b * H_);
    const float4* w4 = (const float4*)(W + (size_t)o * H_);
    float acc = 0.f;
#pragma unroll 8
    for (int k = 0; k < H_ / 4; k++) {
        float4 hh = h4[k], ww = w4[k];
        acc += hh.x * ww.x + hh.y * ww.y + hh.z * ww.z + hh.w * ww.w;
    }
    g_wh[b * H_ + o] = acc;
}

// ---------------------------------------------------------------------------
// Score GEMM v9: 128x128 tile, BK=16, 64 iters, double-buffered 2x24KB.
// 256 threads (8 warps 4m x 2n, 32x64/warp), occ 2.
// ---------------------------------------------------------------------------
#define BK      16
#define NC      (H_ / BK)          // 64
#define RSTR    48                 // 16 bf16 = 32B + 16B pad (R6-verified)
#define PIECE   (128 * RSTR)       // 6144
#define EH      0
#define EL      PIECE
#define UH      (2 * PIECE)
#define UL      (3 * PIECE)
#define STG     (4 * PIECE)        // 24576 per stage
#define SM_SZ   (2 * STG)          // 49152 = 48KB static (R6 proved the size)

__global__ void __launch_bounds__(256, 2)
score_mma_kernel(const float* __restrict__ E,
                 const float* __restrict__ v) {
    __shared__ __align__(16) char smem[SM_SZ];
    const uint32_t sb = smem_u32(smem);

    const int t    = threadIdx.x;
    const int wid  = t >> 5;
    const int lane = t & 31;
    const int q    = lane & 3;
    const int rr   = lane >> 2;
    const int wm   = (wid & 3) * 32;
    const int wni  = wid >> 2;          // 0..1
    const int wn   = wni * 64;
    const int o0   = blockIdx.x * 128;
    const int m0   = blockIdx.y * 128;
    const int b    = m0 >> 11;

    float cacc[2][8][4];
#pragma unroll
    for (int mf = 0; mf < 2; mf++)
#pragma unroll
        for (int nf = 0; nf < 8; nf++)
#pragma unroll
            for (int d = 0; d < 4; d++) cacc[mf][nf][d] = 0.f;

    // staging map: thread -> (row = t>>1, half = t&1); 16B piece per plane
    const int srow = t >> 1;
    const int shalf = t & 1;
    const uint32_t s_off = (uint32_t)(srow * RSTR + shalf * 16);
    const float4* E4  = (const float4*)E;
    const uint4*  Uh4 = (const uint4*)g_U2hi;
    const uint4*  Ul4 = (const uint4*)g_U2lo;
    // E float4 base index for (row srow, chunk c, half): (m0+srow)*256 + c*4 + shalf*2
    const size_t e_base = (size_t)(m0 + srow) * 256 + shalf * 2;
    const size_t u_base = (size_t)(o0 + srow) * 128 + shalf;

    // ldmatrix lane->offset maps (R6-verified for RSTR=48)
    const uint32_t a_off = (uint32_t)((lane & 15) * RSTR + (lane >> 4) * 16);
    const uint32_t b_off = (uint32_t)(((lane & 7) + ((lane >> 4) & 1) * 8) * RSTR
                                      + ((lane >> 3) & 1) * 16);

    // --- prologue: stage chunk 0 into buf0; preload E chunk 1 into regs ---
    float4 e0 = E4[e_base], e1 = E4[e_base + 1];       // chunk 0
    {
        uint4 Hh, Ll;
        split_pack8(e0, e1, Hh, Ll);
        *(uint4*)(smem + EH + s_off) = Hh;
        *(uint4*)(smem + EL + s_off) = Ll;
        CP_ASYNC16(sb + UH + s_off, Uh4 + u_base);
        CP_ASYNC16(sb + UL + s_off, Ul4 + u_base);
        CP_ASYNC_COMMIT();
    }
    e0 = E4[e_base + 4]; e1 = E4[e_base + 5];          // chunk 1 -> regs

#pragma unroll 1
    for (int c = 0; c < NC; c++) {
        CP_ASYNC_WAIT0();
        __syncthreads();                // stage(c) ready; buf[(c+1)&1] free
        if (c + 1 < NC) {
            const uint32_t nb = (uint32_t)(((c + 1) & 1) * STG);
            uint4 Hh, Ll;
            split_pack8(e0, e1, Hh, Ll);               // chunk c+1 from regs
            *(uint4*)(smem + nb + EH + s_off) = Hh;
            *(uint4*)(smem + nb + EL + s_off) = Ll;
            CP_ASYNC16(sb + nb + UH + s_off, Uh4 + u_base + (size_t)(c + 1) * 2);
            CP_ASYNC16(sb + nb + UL + s_off, Ul4 + u_base + (size_t)(c + 1) * 2);
            CP_ASYNC_COMMIT();
            if (c + 2 < NC) {                          // prefetch chunk c+2
                e0 = E4[e_base + (size_t)(c + 2) * 4];
                e1 = E4[e_base + (size_t)(c + 2) * 4 + 1];
            }
        }
        // ---- compute chunk c on buf[c&1] ----
        const uint32_t stg = sb + (uint32_t)((c & 1) * STG);
        uint32_t a[2][2][4];            // [split][mf]
#pragma unroll
        for (int s = 0; s < 2; s++) {
            uint32_t base = stg + (s ? EL : EH) + a_off;
            LDSM_X4(a[s][0][0], a[s][0][1], a[s][0][2], a[s][0][3],
                    base + (uint32_t)(wm * RSTR));
            LDSM_X4(a[s][1][0], a[s][1][1], a[s][1][2], a[s][1][3],
                    base + (uint32_t)((wm + 16) * RSTR));
        }
#pragma unroll
        for (int g = 0; g < 4; g++) {   // nf groups of 2
            uint32_t bb[2][2][2];       // [split][nf-in-group]
#pragma unroll
            for (int s = 0; s < 2; s++) {
                uint32_t base = stg + (s ? UL : UH) + b_off
                              + (uint32_t)((wn + g * 16) * RSTR);
                LDSM_X4(bb[s][0][0], bb[s][0][1], bb[s][1][0], bb[s][1][1],
                        base);
            }
#pragma unroll
            for (int n2 = 0; n2 < 2; n2++)
#pragma unroll
                for (int mf = 0; mf < 2; mf++)
                    MMA16816(cacc[mf][g * 2 + n2], a[0][mf], bb[0][n2]); // hi*hi
#pragma unroll
            for (int n2 = 0; n2 < 2; n2++)
#pragma unroll
                for (int mf = 0; mf < 2; mf++)
                    MMA16816(cacc[mf][g * 2 + n2], a[0][mf], bb[1][n2]); // hi*lo
#pragma unroll
            for (int n2 = 0; n2 < 2; n2++)
#pragma unroll
                for (int mf = 0; mf < 2; mf++)
                    MMA16816(cacc[mf][g * 2 + n2], a[1][mf], bb[0][n2]); // lo*hi
        }
    }

    // Epilogue: p_row = sum_cols v[col]*tanh(acc + wh[col]); v/wh via L2.
    float vv[8][2], wwv[8][2];
#pragma unroll
    for (int nf = 0; nf < 8; nf++)
#pragma unroll
        for (int par = 0; par < 2; par++) {
            int col = o0 + wn + nf * 8 + 2 * q + par;
            vv[nf][par]  = v[col];
            wwv[nf][par] = g_wh[b * H_ + col];
        }
    float pr[2][2] = {{0.f, 0.f}, {0.f, 0.f}};
#pragma unroll
    for (int mf = 0; mf < 2; mf++)
#pragma unroll
        for (int nf = 0; nf < 8; nf++)
#pragma unroll
            for (int d = 0; d < 4; d++)
                pr[mf][d >> 1] += vv[nf][d & 1] *
                    fast_tanh(cacc[mf][nf][d] + wwv[nf][d & 1]);
#pragma unroll
    for (int mf = 0; mf < 2; mf++)
#pragma unroll
        for (int h = 0; h < 2; h++) {
            float p = pr[mf][h];
            p += __shfl_xor_sync(0xffffffffu, p, 1);
            p += __shfl_xor_sync(0xffffffffu, p, 2);
            pr[mf][h] = p;
        }
    __syncthreads();
    float* sred = (float*)smem;
    if (q == 0) {
#pragma unroll
        for (int mf = 0; mf < 2; mf++)
#pragma unroll
            for (int h = 0; h < 2; h++) {
                int row = wm + mf * 16 + h * 8 + rr;
                sred[row * 2 + wni] = pr[mf][h];
            }
    }
    __syncthreads();
    if (t < 128)
        g_spart[(size_t)blockIdx.x * M_ + m0 + t] = sred[t * 2] + sred[t * 2 + 1];
}

// ---------------------------------------------------------------------------
__global__ void softmax_kernel(float* __restrict__ out) {
    __shared__ float buf[S_];
    __shared__ float red[256];
    const int b = blockIdx.x, t = threadIdx.x;

    float mx = -1e30f;
    for (int s = t; s < S_; s += 256) {
        float sc = 0.f;
#pragma unroll
        for (int p = 0; p < NOT; p++) sc += g_spart[(size_t)p * M_ + b * S_ + s];
        buf[s] = sc;
        mx = fmaxf(mx, sc);
    }
    red[t] = mx; __syncthreads();
    for (int o = 128; o > 0; o >>= 1) {
        if (t < o) red[t] = fmaxf(red[t], red[t + o]);
        __syncthreads();
    }
    mx = red[0]; __syncthreads();

    float sum = 0.f;
    for (int s = t; s < S_; s += 256) {
        float e = __expf(buf[s] - mx);
        buf[s] = e;
        sum += e;
    }
    red[t] = sum; __syncthreads();
    for (int o = 128; o > 0; o >>= 1) {
        if (t < o) red[t] += red[t + o];
        __syncthreads();
    }
    float inv = 1.0f / red[0];

    float* attn = out + B_ * H_;
    for (int s = t; s < S_; s += 256)
        attn[b * S_ + s] = buf[s] * inv;
}

__global__ void ctx_part_kernel(const float* __restrict__ E,
                                const float* __restrict__ out) {
    __shared__ float a[128];
    const int sc = blockIdx.x, b = blockIdx.y, t = threadIdx.x;
    const float* attn = out + B_ * H_;
    if (t < 128) a[t] = attn[b * S_ + sc * 128 + t];
    __syncthreads();

    const float4* E4 = (const float4*)E;
    float4 acc = make_float4(0.f, 0.f, 0.f, 0.f);
    int base = (b * S_ + sc * 128) * (H_ / 4) + t;
#pragma unroll 4
    for (int s = 0; s < 128; s++) {
        float w = a[s];
        float4 e = E4[base + s * (H_ / 4)];
        acc.x += w * e.x; acc.y += w * e.y;
        acc.z += w * e.z; acc.w += w * e.w;
    }
    ((float4*)g_cpart)[(sc * B_ + b) * (H_ / 4) + t] = acc;
}

__global__ void ctx_reduce_kernel(float* __restrict__ out) {
    int i = blockIdx.x * 256 + threadIdx.x;
    float s = 0.f;
#pragma unroll
    for (int p = 0; p < NSC; p++) s += g_cpart[p * (B_ * H_) + i];
    out[i] = s;
}

// ---------------------------------------------------------------------------
extern "C" void kernel_launch(void* const* d_in, const int* in_sizes, int n_in,
                              void* d_out, int out_size) {
    const float* hidden = (const float*)d_in[0];
    const float* E      = (const float*)d_in[1];
    const float* W      = (const float*)d_in[2];
    const float* U      = (const float*)d_in[3];
    const float* v      = (const float*)d_in[4];
    float* out = (float*)d_out;

    noop_kernel<<<1, 32>>>();                               // launch 1
    prep_U_kernel<<<H_ * H_ / 8 / 256, 256>>>(U);           // launch 2
    wh_kernel<<<dim3(32, 4), 256>>>(hidden, W);             // launch 3
    score_mma_kernel<<<dim3(NOT, M_ / 128), 256>>>(E, v);   // launch 4 (ncu)
    softmax_kernel<<<B_, 256>>>(out);
    ctx_part_kernel<<<dim3(NSC, B_), 256>>>(E, out);
    ctx_reduce_kernel<<<(B_ * H_) / 256, 256>>>(out);
}